// round 3
// baseline (speedup 1.0000x reference)
#include <cuda_runtime.h>
#include <cuda_bf16.h>

#define V_DIM 32
#define NB 14          // N_BASIS
#define NP 496         // V*(V-1)/2
#define NW 16          // warps per block
#define NTHREADS 512
#define GRID 296       // 2 blocks/SM on 148 SMs

struct WarpScratch {
    float4 Ls4[256];   // lm row tile [32][32], diag/upper pre-initialized
    float4 Bs4[32];    // basis quadruple per column
    float4 xs4[8];     // input row as 8 float4
    int    PT[32];     // per-column params row base = j0*NP
};

struct SmemLayout {
    float P[NB * NP];          // staged params (27776 B)
    WarpScratch w[NW];         // 4864 B per warp
    float red[3][NW];
};

__global__ __launch_bounds__(NTHREADS, 2)
void decor_kernel(const float* __restrict__ input,
                  const float* __restrict__ params,
                  float* __restrict__ d_out,
                  float* __restrict__ scal,
                  int n)
{
    extern __shared__ char smem_raw[];
    SmemLayout* S = reinterpret_cast<SmemLayout*>(smem_raw);

    const int tid  = threadIdx.x;
    const int warp = tid >> 5;
    const int lane = tid & 31;

    // ---- stage params once per block ----
    for (int i = tid; i < NB * NP; i += NTHREADS) S->P[i] = params[i];

    WarpScratch* W = &S->w[warp];
    float* Ls = reinterpret_cast<float*>(W->Ls4);
    float* xs = reinterpret_cast<float*>(W->xs4);

    // one-time init: identity diag + zero upper (lam never touches these)
    for (int idx = lane; idx < 1024; idx += 32) {
        int v = idx >> 5, c = idx & 31;
        Ls[idx] = (v == c) ? 1.0f : 0.0f;
    }

    // row-independent pair geometry: for p = lane + 32*i, A[i] = v*32 - v(v-1)/2
    int A[16];
    #pragma unroll
    for (int i = 0; i < 16; i++) {
        int p = lane + 32 * i;
        int v = (int)((1.0f + sqrtf(8.0f * (float)p + 1.0f)) * 0.5f);
        while (v * (v + 1) / 2 <= p) v++;
        while (v * (v - 1) / 2 > p) v--;
        A[i] = v * 32 - v * (v - 1) / 2;
    }
    __syncthreads();

    // ---- block 0: fused penalties from smem-staged params ----
    if (blockIdx.x == 0) {
        float s0 = 0.f, s1 = 0.f, s2 = 0.f;
        for (int i = tid; i < NB * NP; i += NTHREADS) {
            float p0 = S->P[i];
            s0 += p0 * p0;
            int k = i / NP;
            if (k < NB - 1) {
                float p1 = S->P[i + NP];
                float a = p1 - p0;
                s1 += a * a;
                if (k < NB - 2) {
                    float b = S->P[i + 2 * NP] - 2.0f * p1 + p0;
                    s2 += b * b;
                }
            }
        }
        #pragma unroll
        for (int off = 16; off > 0; off >>= 1) {
            s0 += __shfl_down_sync(0xffffffffu, s0, off);
            s1 += __shfl_down_sync(0xffffffffu, s1, off);
            s2 += __shfl_down_sync(0xffffffffu, s2, off);
        }
        if (lane == 0) { S->red[0][warp] = s2; S->red[1][warp] = s1; S->red[2][warp] = s0; }
        __syncthreads();
        if (tid < 3) {
            float t = 0.f;
            #pragma unroll
            for (int w2 = 0; w2 < NW; w2++) t += S->red[tid][w2];
            scal[tid] = t;   // [0]=second, [1]=first, [2]=param
        }
    }

    const float LOv = -15.0f, HIv = 15.0f;
    const float inv_dist = 11.0f / 30.0f;

    float* lm = d_out + (size_t)n * V_DIM;
    const int row_stride = gridDim.x * NW;

    for (int row = blockIdx.x * NW + warp; row < n; row += row_stride) {

        // load input row (coalesced) + stage for dot
        float xi = input[(size_t)row * V_DIM + lane];
        xs[lane] = xi;

        // cubic uniform B-spline: 4 nonzero funcs, closed form, packed float4
        if (lane < 31) {
            float xc = fminf(fmaxf(xi, LOv), HIv - 1e-6f);
            float s  = (xc - LOv) * inv_dist;       // in [0, 11)
            int j0 = (int)s;
            j0 = min(j0, 10);
            float u  = s - (float)j0;
            float um = 1.0f - u;
            float u2 = u * u, u3 = u2 * u;
            W->Bs4[lane] = make_float4(
                um * um * um * (1.0f / 6.0f),
                (3.0f * u3 - 6.0f * u2 + 4.0f) * (1.0f / 6.0f),
                (-3.0f * u3 + 3.0f * u2 + 3.0f * u + 1.0f) * (1.0f / 6.0f),
                u3 * (1.0f / 6.0f));
            W->PT[lane] = j0 * NP;
        }
        __syncwarp();

        // lam: per value = 1 LDS.128 (basis) + 1 LDS (row base) + 4 LDS (P) + 1 STS
        #pragma unroll
        for (int i = 0; i < 16; i++) {
            int p = lane + 32 * i;
            if (p < NP) {
                int idx = A[i] + p;          // = v*32 + c
                int c   = idx & 31;
                float4 B = W->Bs4[c];
                const float* Pp = S->P + W->PT[c] + p;
                float l = B.x * Pp[0];
                l = fmaf(B.y, Pp[NP],     l);
                l = fmaf(B.z, Pp[2 * NP], l);
                l = fmaf(B.w, Pp[3 * NP], l);
                Ls[idx] = l;
            }
        }
        __syncwarp();

        // lm store (1 LDS.128 + 1 STG.128 per lane-iter) with fused out = lm @ x
        float4* lmrow = reinterpret_cast<float4*>(lm + (size_t)row * V_DIM * V_DIM);
        #pragma unroll
        for (int i = 0; i < 8; i++) {
            int t4 = lane + 32 * i;          // float4 index == v*8 + c0/4
            float4 vals = W->Ls4[t4];
            float4 x4   = W->xs4[t4 & 7];
            __stcs(&lmrow[t4], vals);
            float dv = vals.x * x4.x + vals.y * x4.y + vals.z * x4.z + vals.w * x4.w;
            dv += __shfl_xor_sync(0xffffffffu, dv, 4, 8);
            dv += __shfl_xor_sync(0xffffffffu, dv, 2, 8);
            dv += __shfl_xor_sync(0xffffffffu, dv, 1, 8);
            if ((lane & 7) == 0)
                d_out[(size_t)row * V_DIM + (t4 >> 3)] = dv;   // t4>>3 == v
        }
        __syncwarp();   // protect per-warp scratch before next row
    }
}

extern "C" void kernel_launch(void* const* d_in, const int* in_sizes, int n_in,
                              void* d_out, int out_size)
{
    const float* input  = (const float*)d_in[0];
    // d_in[1] = log_d (unused by the reference's outputs)
    const float* params = (const float*)d_in[2];
    float* outp = (float*)d_out;
    int n = in_sizes[0] / V_DIM;

    float* scal = outp + (size_t)n * V_DIM + (size_t)n * V_DIM * V_DIM;

    size_t smem = sizeof(SmemLayout);
    cudaFuncSetAttribute(decor_kernel, cudaFuncAttributeMaxDynamicSharedMemorySize, (int)smem);

    decor_kernel<<<GRID, NTHREADS, smem>>>(input, params, outp, scal, n);
}